// round 6
// baseline (speedup 1.0000x reference)
#include <cuda_runtime.h>
#include <math.h>
#include <stdint.h>

#define T_STEPS 256
#define BATCH   128
#define DIM     128
#define HID     1024
#define G4      4096      // 4*HID
#define NT      32        // hidden tiles per layer (HID/NH)
#define NH      32        // hidden units per tile -> 128 z columns
#define KS      4         // split-K factor
#define NBLK    128       // persistent blocks = KS*NT (all resident on 148 SMs)
#define NTHR    256

// ---------------- device scratch (endorsed by harness rules) ------------------
__device__ __align__(16) float g_h2all[(size_t)T_STEPS * BATCH * HID];
__device__ __align__(16) float g_logits[(size_t)T_STEPS * BATCH * DIM];
__device__ __align__(16) float g_zpart[(size_t)KS * NT * BATCH * 128];
__device__ __align__(16) float g_h1[BATCH * HID];
__device__ __align__(16) float g_h2[BATCH * HID];
__device__ __align__(16) float g_c1[BATCH * HID];
__device__ __align__(16) float g_c2[BATCH * HID];
__device__ __align__(16) float g_lossbuf[T_STEPS * BATCH];
__device__ volatile unsigned g_bar_gen;   // zero-initialized at module load
__device__ unsigned g_bar_cnt;

__device__ __forceinline__ float sigm(float x) {
    return 1.0f / (1.0f + __expf(-x));
}

// packed fp32x2 helpers (FFMA2 path — ptxas never emits it from C++)
__device__ __forceinline__ void ffma2(unsigned long long& d,
                                      unsigned long long a,
                                      unsigned long long b) {
    asm("fma.rn.f32x2 %0, %1, %2, %0;" : "+l"(d) : "l"(a), "l"(b));
}
__device__ __forceinline__ unsigned long long pack2(float x) {
    unsigned long long r;
    asm("mov.b64 %0, {%1, %1};" : "=l"(r) : "f"(x));
    return r;
}
__device__ __forceinline__ float2 unpack2(unsigned long long v) {
    float2 r;
    asm("mov.b64 {%0, %1}, %2;" : "=f"(r.x), "=f"(r.y) : "l"(v));
    return r;
}

// ---------------- grid-wide barrier (all NBLK blocks resident) ----------------
__device__ __forceinline__ void grid_barrier() {
    __syncthreads();
    __threadfence();
    if (threadIdx.x == 0) {
        unsigned gen = g_bar_gen;            // read BEFORE arriving
        if (atomicAdd(&g_bar_cnt, 1u) == NBLK - 1) {
            g_bar_cnt = 0;
            __threadfence();
            g_bar_gen = gen + 1;             // release
        } else {
            while (g_bar_gen == gen) { __nanosleep(64); }
        }
    }
    __syncthreads();
}

// ---------------- GEMM phase for one layer (writes split-K partials) ----------
// LAYER 1: A = [x_t (128) | h1 (1024)], Ktot=1152 ; LAYER 2: A = [h1 | h2], 2048
// tile columns: c in [0,128) -> global z col (c/32)*HID + tile*32 + c%32
template <int LAYER>
__device__ void gemm_phase(const float* __restrict__ x0, const float* __restrict__ W,
                           int t, int ks, int tile,
                           float (*As)[128], float (*Bs)[128])
{
    constexpr int KTOT = (LAYER == 1) ? (DIM + HID) : (2 * HID);
    constexpr int XD   = (LAYER == 1) ? DIM : HID;
    constexpr int KC   = KTOT / KS;
    constexpr int LDA0 = (LAYER == 1) ? DIM : HID;

    const float* A0 = (LAYER == 1) ? (x0 + (size_t)t * BATCH * DIM) : g_h1;
    const float* A1 = (LAYER == 1) ? g_h1 : g_h2;

    int nb = tile * NH;
    int tid = threadIdx.x;
    int tx = tid & 15, ty = tid >> 4;

    unsigned long long acc2[8][4];
#pragma unroll
    for (int i = 0; i < 8; i++)
#pragma unroll
        for (int j = 0; j < 4; j++) acc2[i][j] = 0ull;

    int kbase = ks * KC;

    for (int k0 = 0; k0 < KC; k0 += 16) {
        int kg = kbase + k0;
        const float* Asrc;
        int koff, lda;
        if (kg < XD) { Asrc = A0; koff = kg;      lda = LDA0; }
        else         { Asrc = A1; koff = kg - XD; lda = HID;  }
#pragma unroll
        for (int r = 0; r < 2; r++) {
            int p = tid + r * 256;
            int m = p >> 2, kq = (p & 3) * 4;
            float4 v = *(const float4*)(Asrc + (size_t)m * lda + koff + kq);
            As[kq + 0][m] = v.x; As[kq + 1][m] = v.y;
            As[kq + 2][m] = v.z; As[kq + 3][m] = v.w;
        }
#pragma unroll
        for (int r = 0; r < 2; r++) {
            int p = tid + r * 256;
            int kk = p >> 5, c4 = (p & 31) * 4;
            int col = (c4 >> 5) * HID + nb + (c4 & 31);
            float4 v = *(const float4*)(W + (size_t)(kg + kk) * G4 + col);
            *(float4*)&Bs[kk][c4] = v;
        }
        __syncthreads();
#pragma unroll
        for (int k = 0; k < 16; k++) {
            float4 a0 = *(const float4*)&As[k][ty * 4];
            float4 a1 = *(const float4*)&As[k][ty * 4 + 64];
            // b pairs: reinterpret 16B shared chunks as packed f32x2 (free)
            ulonglong2 bb0 = *(const ulonglong2*)&Bs[k][tx * 4];
            ulonglong2 bb1 = *(const ulonglong2*)&Bs[k][tx * 4 + 64];
            unsigned long long b2[4] = {bb0.x, bb0.y, bb1.x, bb1.y};
            float av[8] = {a0.x, a0.y, a0.z, a0.w, a1.x, a1.y, a1.z, a1.w};
#pragma unroll
            for (int i = 0; i < 8; i++) {
                unsigned long long a2 = pack2(av[i]);
#pragma unroll
                for (int j = 0; j < 4; j++)
                    ffma2(acc2[i][j], a2, b2[j]);
            }
        }
        __syncthreads();
    }

    float* zp = g_zpart + ((size_t)ks * NT + tile) * (BATCH * 128);
#pragma unroll
    for (int i = 0; i < 8; i++) {
        int m = (i < 4) ? (ty * 4 + i) : (64 + ty * 4 + i - 4);
        float* zr = zp + (size_t)m * 128;
        *(float2*)(zr + tx * 4)          = unpack2(acc2[i][0]);
        *(float2*)(zr + tx * 4 + 2)      = unpack2(acc2[i][1]);
        *(float2*)(zr + tx * 4 + 64)     = unpack2(acc2[i][2]);
        *(float2*)(zr + tx * 4 + 66)     = unpack2(acc2[i][3]);
    }
}

// ---------------- gate phase: reduce split-K partials + LSTM nonlinearity -----
template <int LAYER>
__device__ void gate_phase(const float* __restrict__ bias, int t, int gid)
{
    const float* cbuf = (LAYER == 1) ? g_c1 : g_c2;
    float* cw = (LAYER == 1) ? g_c1 : g_c2;
    float* hw = (LAYER == 1) ? g_h1 : g_h2;

#pragma unroll
    for (int e = 0; e < (BATCH * HID) / (NBLK * NTHR); e++) {
        int idx = gid + e * (NBLK * NTHR);
        int b  = idx >> 10;
        int hg = idx & (HID - 1);
        int tile = hg >> 5;
        int hh = hg & 31;

        float zi = 0.f, zj = 0.f, zf = 0.f, zo = 0.f;
#pragma unroll
        for (int s = 0; s < KS; s++) {
            const float* z = g_zpart + ((size_t)s * NT + tile) * (BATCH * 128)
                           + (size_t)b * 128;
            zi += z[hh]; zj += z[32 + hh]; zf += z[64 + hh]; zo += z[96 + hh];
        }
        zi += bias[hg];
        zj += bias[HID + hg];
        zf += bias[2 * HID + hg];
        zo += bias[3 * HID + hg];

        float cp = cbuf[idx];
        float fg = sigm(zf + 1.0f);
        float ig = sigm(zi);
        float jg = tanhf(zj);
        float og = sigm(zo);
        float cn = cp * fg + ig * jg;
        float hn = tanhf(cn) * og;
        cw[idx] = cn;
        hw[idx] = hn;
        if (LAYER == 2)
            g_h2all[(size_t)t * BATCH * HID + idx] = hn;
    }
}

// ---------------- persistent recurrence kernel: all 256 steps, 1 launch -------
__global__ __launch_bounds__(NTHR, 1) void lstm_persistent_kernel(
    const float* __restrict__ inSeq,
    const float* __restrict__ W1, const float* __restrict__ b1,
    const float* __restrict__ W2, const float* __restrict__ b2)
{
    __shared__ __align__(16) float As[16][128];
    __shared__ __align__(16) float Bs[16][128];

    int bid = blockIdx.x;
    int tile = bid & 31, ks = bid >> 5;
    int gid = bid * NTHR + threadIdx.x;

    // zero initial state
    for (int i = gid; i < BATCH * HID; i += NBLK * NTHR) {
        g_h1[i] = 0.f; g_h2[i] = 0.f; g_c1[i] = 0.f; g_c2[i] = 0.f;
    }
    grid_barrier();

    for (int t = 0; t < T_STEPS; t++) {
        gemm_phase<1>(inSeq, W1, t, ks, tile, As, Bs);
        grid_barrier();
        gate_phase<1>(b1, t, gid);
        grid_barrier();
        gemm_phase<2>(nullptr, W2, t, ks, tile, As, Bs);
        grid_barrier();
        gate_phase<2>(b2, t, gid);
        grid_barrier();
    }
}

// ---------------- logits = g_h2all @ outW + outB ------------------------------
__global__ __launch_bounds__(256) void logits_kernel(
    const float* __restrict__ W,      // outW [HID][DIM]
    const float* __restrict__ bias)   // outB [DIM]
{
    int mt = blockIdx.x;
    __shared__ __align__(16) float As[16][128];
    __shared__ __align__(16) float Bs[16][128];
    int tid = threadIdx.x;
    int tx = tid & 15, ty = tid >> 4;
    float acc[8][8];
#pragma unroll
    for (int i = 0; i < 8; i++)
#pragma unroll
        for (int j = 0; j < 8; j++) acc[i][j] = 0.f;

    const float* Ab = g_h2all + (size_t)mt * 128 * HID;

    for (int k0 = 0; k0 < HID; k0 += 16) {
#pragma unroll
        for (int r = 0; r < 2; r++) {
            int p = tid + r * 256;
            int m = p >> 2, kq = (p & 3) * 4;
            float4 v = *(const float4*)(Ab + (size_t)m * HID + k0 + kq);
            As[kq + 0][m] = v.x; As[kq + 1][m] = v.y;
            As[kq + 2][m] = v.z; As[kq + 3][m] = v.w;
        }
#pragma unroll
        for (int r = 0; r < 2; r++) {
            int p = tid + r * 256;
            int kk = p >> 5, c4 = (p & 31) * 4;
            float4 v = *(const float4*)(W + (size_t)(k0 + kk) * DIM + c4);
            *(float4*)&Bs[kk][c4] = v;
        }
        __syncthreads();
#pragma unroll
        for (int k = 0; k < 16; k++) {
            float4 a0 = *(const float4*)&As[k][ty * 4];
            float4 a1 = *(const float4*)&As[k][ty * 4 + 64];
            float4 b0 = *(const float4*)&Bs[k][tx * 4];
            float4 b1 = *(const float4*)&Bs[k][tx * 4 + 64];
            float av[8] = {a0.x, a0.y, a0.z, a0.w, a1.x, a1.y, a1.z, a1.w};
            float bv[8] = {b0.x, b0.y, b0.z, b0.w, b1.x, b1.y, b1.z, b1.w};
#pragma unroll
            for (int i = 0; i < 8; i++)
#pragma unroll
                for (int j = 0; j < 8; j++)
                    acc[i][j] = fmaf(av[i], bv[j], acc[i][j]);
        }
        __syncthreads();
    }

#pragma unroll
    for (int i = 0; i < 8; i++) {
        int m = (i < 4) ? (ty * 4 + i) : (64 + ty * 4 + i - 4);
        float* orow = g_logits + (size_t)(mt * 128 + m) * DIM;
        int c0 = tx * 4;
        float4 o0, o1;
        o0.x = acc[i][0] + bias[c0 + 0];
        o0.y = acc[i][1] + bias[c0 + 1];
        o0.z = acc[i][2] + bias[c0 + 2];
        o0.w = acc[i][3] + bias[c0 + 3];
        o1.x = acc[i][4] + bias[c0 + 64];
        o1.y = acc[i][5] + bias[c0 + 65];
        o1.z = acc[i][6] + bias[c0 + 66];
        o1.w = acc[i][7] + bias[c0 + 67];
        *(float4*)(orow + c0) = o0;
        *(float4*)(orow + c0 + 64) = o1;
    }
}

// ---------------- dual softmax + probs + CE (warp per row) --------------------
// targets are int32 (JAX x64-disabled: astype(int64) is a no-op)
__global__ __launch_bounds__(256) void softmax_ce_kernel(
    const int* __restrict__ tgt,
    float* __restrict__ probs)
{
    int warp = (blockIdx.x * blockDim.x + threadIdx.x) >> 5;
    int lane = threadIdx.x & 31;
    if (warp >= T_STEPS * BATCH) return;
    const float* row = g_logits + (size_t)warp * 128;
    float v0 = row[lane], v1 = row[lane + 32], v2 = row[lane + 64], v3 = row[lane + 96];

    float m_mel = fmaxf(v0, lane < 16 ? v1 : -1e30f);
#pragma unroll
    for (int o = 16; o; o >>= 1) m_mel = fmaxf(m_mel, __shfl_xor_sync(~0u, m_mel, o));
    float e0 = __expf(v0 - m_mel);
    float e1m = (lane < 16) ? __expf(v1 - m_mel) : 0.f;
    float s_mel = e0 + e1m;
#pragma unroll
    for (int o = 16; o; o >>= 1) s_mel += __shfl_xor_sync(~0u, s_mel, o);

    float m_har = fmaxf(fmaxf(v2, v3), lane >= 16 ? v1 : -1e30f);
#pragma unroll
    for (int o = 16; o; o >>= 1) m_har = fmaxf(m_har, __shfl_xor_sync(~0u, m_har, o));
    float e1h = (lane >= 16) ? __expf(v1 - m_har) : 0.f;
    float e2 = __expf(v2 - m_har);
    float e3 = __expf(v3 - m_har);
    float s_har = e1h + e2 + e3;
#pragma unroll
    for (int o = 16; o; o >>= 1) s_har += __shfl_xor_sync(~0u, s_har, o);

    float inv_mel = 1.0f / s_mel;
    float inv_har = 1.0f / s_har;
    float* pr = probs + (size_t)warp * 128;
    pr[lane]      = e0 * inv_mel;
    pr[lane + 32] = (lane < 16) ? e1m * inv_mel : e1h * inv_har;
    pr[lane + 64] = e2 * inv_har;
    pr[lane + 96] = e3 * inv_har;

    if (lane == 0) {
        int t0 = tgt[warp * 2 + 0];
        int t1 = tgt[warp * 2 + 1];
        t0 = min(max(t0, 0), 47);
        t1 = min(max(t1, 0), 79);
        float l0 = row[t0];
        float l1 = row[48 + t1];
        float lse_mel = m_mel + logf(s_mel);
        float lse_har = m_har + logf(s_har);
        g_lossbuf[warp] = 0.5f * (lse_mel - l0) + 0.5f * (lse_har - l1);
    }
}

__global__ __launch_bounds__(256) void loss_reduce_kernel(float* __restrict__ out)
{
    __shared__ float sm[256];
    float s = 0.f;
    for (int i = threadIdx.x; i < T_STEPS * BATCH; i += 256) s += g_lossbuf[i];
    sm[threadIdx.x] = s;
    __syncthreads();
    for (int o = 128; o; o >>= 1) {
        if (threadIdx.x < o) sm[threadIdx.x] += sm[threadIdx.x + o];
        __syncthreads();
    }
    if (threadIdx.x == 0)
        out[0] = sm[0] / (float)(T_STEPS * BATCH);
}

// ---------------- launch (4 graph nodes total) ---------------------------------
extern "C" void kernel_launch(void* const* d_in, const int* in_sizes, int n_in,
                              void* d_out, int out_size)
{
    const float* inSeq = (const float*)d_in[0];
    const int*   tgt   = (const int*)d_in[1];     // int32 targets
    const float* W1    = (const float*)d_in[2];
    const float* b1    = (const float*)d_in[3];
    const float* W2    = (const float*)d_in[4];
    const float* b2    = (const float*)d_in[5];
    const float* outW  = (const float*)d_in[6];
    const float* outB  = (const float*)d_in[7];
    float* out = (float*)d_out;

    lstm_persistent_kernel<<<NBLK, NTHR>>>(inSeq, W1, b1, W2, b2);

    logits_kernel<<<(T_STEPS * BATCH) / 128, 256>>>(outW, outB);

    softmax_ce_kernel<<<(T_STEPS * BATCH * 32) / 256, 256>>>(tgt, out);

    loss_reduce_kernel<<<1, 256>>>(out + (out_size - 1));
}